// round 4
// baseline (speedup 1.0000x reference)
#include <cuda_runtime.h>
#include <cstddef>

#define BB  256
#define NS0 4096
#define NS1 2048
#define NS2 1024
#define NS3 512
#define E0  32768
#define E1  16384
#define E2  8192
#define DD  64

#define DEG_OFF1 (NS0)
#define DEG_OFF2 (NS0 + NS1)
#define RP_OFF1  (NS0 + 1)
#define RP_OFF2  (NS0 + NS1 + 2)
#define COL_OFF1 (E0)
#define COL_OFF2 (E0 + E1)

// ---------------- scratch (device globals; no allocation) ----------------
__device__ float g_h[(size_t)BB * NS0 * DD];         // 268 MB node features
__device__ float g_als[BB * NS0];
__device__ float g_ald[BB * NS0];
__device__ float g_pool[(size_t)BB * NS1 * DD];      // 134 MB pooled features
__device__ int   g_deg[NS0 + NS1 + NS2];
__device__ int   g_rp[(NS0 + 1) + (NS1 + 1) + (NS2 + 1)];
__device__ int   g_wp[(NS0 + 1) + (NS1 + 1) + (NS2 + 1)];
__device__ int   g_col[E0 + E1 + E2];
__device__ float g_part[256 * 128];                  // BN partial sums
__device__ float g_mean[DD];
__device__ float g_rstd[DD];

__device__ __forceinline__ float lrelu(float x) { return x > 0.f ? x : 0.2f * x; }

// ---------------- CSR build ----------------
__global__ void zero_deg_kernel() {
    int i = blockIdx.x * blockDim.x + threadIdx.x;
    if (i < NS0 + NS1 + NS2) g_deg[i] = 0;
}

__global__ void zero_pool_kernel(int n4) {
    float4 z = make_float4(0.f, 0.f, 0.f, 0.f);
    float4* p = (float4*)g_pool;
    for (int i = blockIdx.x * blockDim.x + threadIdx.x; i < n4; i += gridDim.x * blockDim.x)
        p[i] = z;
}

// one launch handles all 3 edge lists: blocks [0,128) -> e0, [128,192) -> e1, [192,224) -> e2
__global__ void count_all_kernel(const int* __restrict__ e0d,
                                 const int* __restrict__ e1d,
                                 const int* __restrict__ e2d) {
    int b = blockIdx.x;
    const int* e; int epb, degOff, j0;
    if (b < 128)      { e = e0d; epb = E0; degOff = 0;        j0 = b * 256; }
    else if (b < 192) { e = e1d; epb = E1; degOff = DEG_OFF1; j0 = (b - 128) * 256; }
    else              { e = e2d; epb = E2; degOff = DEG_OFF2; j0 = (b - 192) * 256; }
    int j = j0 + threadIdx.x;
    if (j < epb) atomicAdd(&g_deg[degOff + e[epb + j]], 1);   // row 1 = dst
}

__global__ void scatter_all_kernel(const int* __restrict__ e0d,
                                   const int* __restrict__ e1d,
                                   const int* __restrict__ e2d) {
    int b = blockIdx.x;
    const int* e; int epb, rpOff, colOff, j0;
    if (b < 128)      { e = e0d; epb = E0; rpOff = 0;       colOff = 0;        j0 = b * 256; }
    else if (b < 192) { e = e1d; epb = E1; rpOff = RP_OFF1; colOff = COL_OFF1; j0 = (b - 128) * 256; }
    else              { e = e2d; epb = E2; rpOff = RP_OFF2; colOff = COL_OFF2; j0 = (b - 192) * 256; }
    int j = j0 + threadIdx.x;
    if (j < epb) {
        int s = e[j];
        int d = e[epb + j];
        int p = atomicAdd(&g_wp[rpOff + d], 1);
        g_col[colOff + p] = s;
    }
}

// single-block exclusive scan
__global__ void scan_kernel(int degOff, int rpOff, int n) {
    __shared__ int tsum[1024];
    int t = threadIdx.x;
    int chunk = (n + 1023) >> 10;
    int start = t * chunk;
    int s = 0;
    for (int i = 0; i < chunk; i++) {
        int idx = start + i;
        if (idx < n) s += g_deg[degOff + idx];
    }
    tsum[t] = s;
    __syncthreads();
    for (int off = 1; off < 1024; off <<= 1) {
        int v = (t >= off) ? tsum[t - off] : 0;
        __syncthreads();
        tsum[t] += v;
        __syncthreads();
    }
    int run = (t == 0) ? 0 : tsum[t - 1];
    for (int i = 0; i < chunk; i++) {
        int idx = start + i;
        if (idx < n) {
            g_rp[rpOff + idx] = run;
            g_wp[rpOff + idx] = run;
            run += g_deg[degOff + idx];
        }
    }
    if (t == 1023) g_rp[rpOff + n] = tsum[1023];
}

// ---------------- fused GEMM (+optional BN normalize) + attention dots ----------------
// tile: 256 nodes x 64 feats, 256 threads, 8x8 outputs/thread; K chunked by 32.
// SRC: 0 = external pointer (layer 0), 1 = g_pool (layers 1,2 — with BN normalize)
template <int K, int SRC>
__global__ __launch_bounds__(256) void gemm_kernel(
    const float* __restrict__ xin, const float* __restrict__ Wg,
    const float* __restrict__ avs_g, const float* __restrict__ avd_g)
{
    constexpr int KC = (K < 32) ? K : 32;
    __shared__ float xs[KC * 260];
    __shared__ float ws[KC * 68];
    __shared__ float avs[64], avd[64];

    const int t = threadIdx.x;
    const int tc = t & 7;
    const int tr = t >> 3;
    const size_t nodeBase = (size_t)blockIdx.x * 256;
    const float* src = (SRC == 0) ? xin : (const float*)g_pool;

    if (t < 64) { avs[t] = avs_g[t]; avd[t] = avd_g[t]; }

    float acc[8][8];
#pragma unroll
    for (int i = 0; i < 8; i++)
#pragma unroll
        for (int j = 0; j < 8; j++) acc[i][j] = 0.f;

    for (int k0 = 0; k0 < K; k0 += KC) {
        if (k0) __syncthreads();
        for (int idx = t; idx < 256 * KC; idx += 256) {
            int n = idx / KC;
            int k = idx - n * KC;
            float v = src[(nodeBase + n) * K + k0 + k];
            if (SRC == 1) v = (v - g_mean[k0 + k]) * g_rstd[k0 + k];
            xs[k * 260 + n] = v;
        }
        for (int idx = t; idx < KC * 64; idx += 256)
            ws[(idx >> 6) * 68 + (idx & 63)] = Wg[(k0 + (idx >> 6)) * 64 + (idx & 63)];
        __syncthreads();

#pragma unroll 4
        for (int k = 0; k < KC; k++) {
            float a[8], b[8];
#pragma unroll
            for (int i = 0; i < 8; i++) a[i] = xs[k * 260 + tr + 32 * i];
#pragma unroll
            for (int j = 0; j < 8; j++) b[j] = ws[k * 68 + tc * 8 + j];
#pragma unroll
            for (int i = 0; i < 8; i++)
#pragma unroll
                for (int j = 0; j < 8; j++) acc[i][j] = fmaf(a[i], b[j], acc[i][j]);
        }
    }

#pragma unroll
    for (int i = 0; i < 8; i++) {
        size_t n = nodeBase + tr + 32 * i;
        float4 v0 = make_float4(acc[i][0], acc[i][1], acc[i][2], acc[i][3]);
        float4 v1 = make_float4(acc[i][4], acc[i][5], acc[i][6], acc[i][7]);
        *(float4*)&g_h[n * 64 + tc * 8]     = v0;
        *(float4*)&g_h[n * 64 + tc * 8 + 4] = v1;
        float ps = 0.f, pd = 0.f;
#pragma unroll
        for (int j = 0; j < 8; j++) {
            ps = fmaf(acc[i][j], avs[tc * 8 + j], ps);
            pd = fmaf(acc[i][j], avd[tc * 8 + j], pd);
        }
        for (int o = 4; o; o >>= 1) {
            ps += __shfl_xor_sync(0xffffffffu, ps, o);
            pd += __shfl_xor_sync(0xffffffffu, pd, o);
        }
        if (tc == 0) { g_als[n] = ps; g_ald[n] = pd; }
    }
}

// ---------------- GAT edge-softmax + aggregate + bias + relu + cluster max-pool ----------------
// one warp per target node; neighbor loop software-pipelined
__global__ __launch_bounds__(256) void agg_kernel(
    const int* __restrict__ clus, const float* __restrict__ bias,
    int rpOff, int colOff, int nshift, int nsout, int ntot)
{
    int w = (blockIdx.x * blockDim.x + threadIdx.x) >> 5;
    int lane = threadIdx.x & 31;
    if (w >= ntot) return;
    int li = w & ((1 << nshift) - 1);
    int g = w >> nshift;
    size_t base = (size_t)g << nshift;

    float adi = g_ald[w];
    float eself = lrelu(g_als[w] + adi);
    int r0 = g_rp[rpOff + li], r1 = g_rp[rpOff + li + 1];
    const int* col = g_col + colOff;

    // pass 1: max over incoming edges (+self), lanes strided
    float m = eself;
    for (int j = r0 + lane; j < r1; j += 32) {
        float e = lrelu(g_als[base + col[j]] + adi);
        m = fmaxf(m, e);
    }
    for (int o = 16; o; o >>= 1) m = fmaxf(m, __shfl_xor_sync(0xffffffffu, m, o));

    // pass 2: weighted accumulation, pipelined (prefetch next col/als)
    float z = __expf(eself - m);
    float a0 = z * g_h[(size_t)w * 64 + lane];
    float a1 = z * g_h[(size_t)w * 64 + 32 + lane];

    if (r0 < r1) {
        int   sN  = col[r0];
        float alN = g_als[base + sN];
        for (int j = r0; j < r1; j++) {
            int s = sN;
            float al = alN;
            if (j + 1 < r1) {
                sN  = col[j + 1];
                alN = g_als[base + sN];
            }
            float wgt = __expf(lrelu(al + adi) - m);
            z += wgt;
            const float* hr = g_h + (base + s) * 64;
            a0 = fmaf(wgt, hr[lane], a0);
            a1 = fmaf(wgt, hr[32 + lane], a1);
        }
    }

    float inv = __fdividef(1.f, z);
    float o0 = fmaxf(fmaf(a0, inv, bias[lane]), 0.f);
    float o1 = fmaxf(fmaf(a1, inv, bias[32 + lane]), 0.f);

    size_t seg = (size_t)g * nsout + clus[li];
    atomicMax((int*)(g_pool + seg * 64 + lane), __float_as_int(o0));
    atomicMax((int*)(g_pool + seg * 64 + 32 + lane), __float_as_int(o1));
}

// ---------------- BatchNorm statistics (deterministic 2-stage) ----------------
__global__ __launch_bounds__(256) void bn_stats_kernel(int nrows) {
    int f = threadIdx.x & 63;
    int rg = threadIdx.x >> 6;
    float s = 0.f, ss = 0.f;
    for (int r = blockIdx.x * 4 + rg; r < nrows; r += 1024) {
        float v = g_pool[(size_t)r * 64 + f];
        s += v;
        ss = fmaf(v, v, ss);
    }
    __shared__ float sh[2][256];
    sh[0][threadIdx.x] = s;
    sh[1][threadIdx.x] = ss;
    __syncthreads();
    if (threadIdx.x < 64) {
        float S  = sh[0][f] + sh[0][f + 64] + sh[0][f + 128] + sh[0][f + 192];
        float SS = sh[1][f] + sh[1][f + 64] + sh[1][f + 128] + sh[1][f + 192];
        g_part[blockIdx.x * 128 + f]      = S;
        g_part[blockIdx.x * 128 + 64 + f] = SS;
    }
}

__global__ void bn_final_kernel(int nrows) {
    int f = threadIdx.x;   // 64 threads
    double S = 0.0, SS = 0.0;
    for (int b = 0; b < 256; b++) {
        S  += (double)g_part[b * 128 + f];
        SS += (double)g_part[b * 128 + 64 + f];
    }
    double mu  = S / nrows;
    double var = SS / nrows - mu * mu;
    g_mean[f] = (float)mu;
    g_rstd[f] = (float)rsqrt(var + 1e-5);
}

__global__ void finalize_kernel(float* __restrict__ out, int n) {
    int i = blockIdx.x * blockDim.x + threadIdx.x;
    if (i < n) {
        int f = i & 63;
        out[i] = (g_pool[i] - g_mean[f]) * g_rstd[f];
    }
}

// ---------------- host driver ----------------
extern "C" void kernel_launch(void* const* d_in, const int* in_sizes, int n_in,
                              void* d_out, int out_size)
{
    (void)n_in; (void)out_size;
    const float* x = (const float*)d_in[0];
    const float *W[3], *As[3], *Ad[3], *Bi[3];
    const int *E[3], *C[3];

    // disambiguate setup_inputs dict order vs reference signature order
    bool dictOrder = (in_sizes[5] == 2 * E0);
    if (dictOrder) {
        int p = 1;
        for (int l = 0; l < 3; l++) {
            W[l]  = (const float*)d_in[p + 0];
            As[l] = (const float*)d_in[p + 1];
            Ad[l] = (const float*)d_in[p + 2];
            Bi[l] = (const float*)d_in[p + 3];
            E[l]  = (const int*)d_in[p + 4];
            C[l]  = (const int*)d_in[p + 5];
            p += 6;
        }
    } else {
        for (int l = 0; l < 3; l++) {
            W[l]  = (const float*)d_in[1 + 4 * l];
            As[l] = (const float*)d_in[2 + 4 * l];
            Ad[l] = (const float*)d_in[3 + 4 * l];
            Bi[l] = (const float*)d_in[4 + 4 * l];
        }
        E[0] = (const int*)d_in[13]; E[1] = (const int*)d_in[14]; E[2] = (const int*)d_in[15];
        C[0] = (const int*)d_in[16]; C[1] = (const int*)d_in[17]; C[2] = (const int*)d_in[18];
    }

    // ---- CSR build (per-graph edge lists shared across the whole batch) ----
    zero_deg_kernel<<<28, 256>>>();
    count_all_kernel<<<224, 256>>>(E[0], E[1], E[2]);
    scan_kernel<<<1, 1024>>>(0, 0, NS0);
    scan_kernel<<<1, 1024>>>(DEG_OFF1, RP_OFF1, NS1);
    scan_kernel<<<1, 1024>>>(DEG_OFF2, RP_OFF2, NS2);
    scatter_all_kernel<<<224, 256>>>(E[0], E[1], E[2]);

    // ---- layer 0 ----
    gemm_kernel<3, 0><<<(BB * NS0) / 256, 256>>>(x, W[0], As[0], Ad[0]);
    zero_pool_kernel<<<2048, 256>>>(BB * NS1 * DD / 4);
    agg_kernel<<<(BB * NS0 * 32) / 256, 256>>>(C[0], Bi[0], 0, 0, 12, NS1, BB * NS0);
    bn_stats_kernel<<<256, 256>>>(BB * NS1);
    bn_final_kernel<<<1, 64>>>(BB * NS1);

    // ---- layer 1 ----
    gemm_kernel<64, 1><<<(BB * NS1) / 256, 256>>>(nullptr, W[1], As[1], Ad[1]);
    zero_pool_kernel<<<2048, 256>>>(BB * NS2 * DD / 4);
    agg_kernel<<<(BB * NS1 * 32) / 256, 256>>>(C[1], Bi[1], RP_OFF1, COL_OFF1, 11, NS2, BB * NS1);
    bn_stats_kernel<<<256, 256>>>(BB * NS2);
    bn_final_kernel<<<1, 64>>>(BB * NS2);

    // ---- layer 2 ----
    gemm_kernel<64, 1><<<(BB * NS2) / 256, 256>>>(nullptr, W[2], As[2], Ad[2]);
    zero_pool_kernel<<<2048, 256>>>(BB * NS3 * DD / 4);
    agg_kernel<<<(BB * NS2 * 32) / 256, 256>>>(C[2], Bi[2], RP_OFF2, COL_OFF2, 10, NS3, BB * NS2);
    bn_stats_kernel<<<256, 256>>>(BB * NS3);
    bn_final_kernel<<<1, 64>>>(BB * NS3);

    finalize_kernel<<<(BB * NS3 * DD) / 256, 256>>>((float*)d_out, BB * NS3 * DD);
}